// round 5
// baseline (speedup 1.0000x reference)
#include <cuda_runtime.h>

// ----------------------------------------------------------------------------
// KB_Mapping_19361712570541
//   x:[N,128] -> dw3x3(b1) -> relu -> pw(W1) -> relu            (branch 1)
//   x -> pw(W2) -> relu ; += b1p ; * threefry-mask              (b2 pre)
//   -> dw3x3 -> relu -> pw(W3) -> relu                          (b2)
//   out = relu( Wf_a @ x + Wf_b @ b2 )                          (fusion)
// Layout everywhere: row-major [N, C], C = 128.
// Mask: JAX partitionable threefry (default since ~0.4.36):
//   bits[f] = out0 ^ out1 of threefry2x32((0,42), (0, f)); keep = MSB==0.
// ----------------------------------------------------------------------------

#define NTOK     131072
#define CCH      128
#define TM       64
#define NTHREADS 256
#define PITCH    132          // smem row pitch in floats (bank-conflict padding)

typedef unsigned long long ull;

// Scratch (device globals; runtime allocation is forbidden by the harness)
__device__ float g_b2 [(size_t)NTOK * CCH];
__device__ float g_b2p[(size_t)NTOK * CCH];

// ---------------- packed fp32x2 helpers (Blackwell FFMA2) -------------------
__device__ __forceinline__ ull ffma2(ull a, ull b, ull c) {
    ull d;
    asm("fma.rn.f32x2 %0, %1, %2, %3;" : "=l"(d) : "l"(a), "l"(b), "l"(c));
    return d;
}
__device__ __forceinline__ ull splat2(float a) {
    ull d;
    asm("mov.b64 %0, {%1, %1};" : "=l"(d) : "f"(a));
    return d;
}
__device__ __forceinline__ float2 unpack2(ull v) {
    float2 f;
    asm("mov.b64 {%0, %1}, %2;" : "=f"(f.x), "=f"(f.y) : "l"(v));
    return f;
}

// ---------------- threefry-2x32 partitionable mask --------------------------
// jax.random.bernoulli(key(42), 0.5, (1,128,131072,1)), threefry_partitionable
// (default True in modern JAX):
//   count64 = flat index f;  inputs (hi, lo) = (0, f)
//   bits = out0 ^ out1 ;  uniform = ((bits >> 9) | 0x3f800000) - 1
//   keep = uniform < 0.5  <=>  bit31(bits) == 0
__device__ __forceinline__ unsigned int rotl32(unsigned int x, int r) {
    return __funnelshift_l(x, x, r);
}
__device__ __forceinline__ unsigned int keepbit(unsigned int fidx) {
    const unsigned int K0 = 0u;
    const unsigned int K1 = 42u;
    const unsigned int K2 = 0u ^ 42u ^ 0x1BD11BDAu;
    unsigned int x0 = 0u + K0;      // counts_hi = 0
    unsigned int x1 = fidx + K1;    // counts_lo = f
#define TF_R4(a,b,c,d)                                              \
    x0 += x1; x1 = rotl32(x1,(a)); x1 ^= x0;                        \
    x0 += x1; x1 = rotl32(x1,(b)); x1 ^= x0;                        \
    x0 += x1; x1 = rotl32(x1,(c)); x1 ^= x0;                        \
    x0 += x1; x1 = rotl32(x1,(d)); x1 ^= x0;
    TF_R4(13,15,26, 6);  x0 += K1; x1 += K2 + 1u;
    TF_R4(17,29,16,24);  x0 += K2; x1 += K0 + 2u;
    TF_R4(13,15,26, 6);  x0 += K0; x1 += K1 + 3u;
    TF_R4(17,29,16,24);  x0 += K1; x1 += K2 + 4u;
    TF_R4(13,15,26, 6);  x0 += K2; x1 += K0 + 5u;
#undef TF_R4
    return (~(x0 ^ x1)) >> 31;   // 1 = keep (MSB of xor-fold is 0)
}

// ---------------- register-tiled 64x128 @ 128x128 pass ----------------------
// Thread map: lane = tid&31 -> 4 output cols (c0 = lane*4, two packed pairs),
//             warp = tid>>5 -> 8 output rows (r0 = warp*8).
// A-loads are warp-broadcast (1 distinct addr); W-loads are 512B contiguous
// per warp (conflict-free); W pairs come packed directly from LDS.128.
__device__ __forceinline__ void gemm_tile(const float* __restrict__ As,
                                          const float* __restrict__ Wt,
                                          int r0, int c0, ull acc[8][2]) {
#pragma unroll 2
    for (int k = 0; k < CCH; k += 4) {
        ulonglong2 w[4];
#pragma unroll
        for (int kk = 0; kk < 4; kk++)
            w[kk] = *(const ulonglong2*)(Wt + (k + kk) * PITCH + c0);
        float4 a[8];
#pragma unroll
        for (int i = 0; i < 8; i++)
            a[i] = *(const float4*)(As + (r0 + i) * PITCH + k);
#pragma unroll
        for (int kk = 0; kk < 4; kk++) {
#pragma unroll
            for (int i = 0; i < 8; i++) {
                const float* af = (const float*)&a[i];
                ull s = splat2(af[kk]);
                acc[i][0] = ffma2(s, w[kk].x, acc[i][0]);
                acc[i][1] = ffma2(s, w[kk].y, acc[i][1]);
            }
        }
    }
}

// Shared-memory byte sizes
#define SMEM_A  ((2 * CCH * PITCH + 66 * PITCH + TM * PITCH + 3 * CCH) * 4)
#define SMEM_B1 ((    CCH * PITCH + 66 * PITCH + TM * PITCH + 3 * CCH) * 4)
#define SMEM_B2 ((2 * CCH * PITCH + 2 * TM * PITCH) * 4)

// ---------------- Kernel A: dw1 -> pw1 ; pw2 ; add ; mask -> g_b2 -----------
__global__ void __launch_bounds__(NTHREADS)
kA(const float* __restrict__ x, const float* __restrict__ w_dw1,
   const float* __restrict__ w_pw1, const float* __restrict__ w_pw2) {
    extern __shared__ float sm[];
    float* W1t  = sm;                       // [128][PITCH]  (w_b1_pw^T)
    float* W2t  = sm + CCH * PITCH;         // [128][PITCH]  (w_b2_1x1^T)
    float* xs   = sm + 2 * CCH * PITCH;     // [66][PITCH]   rows base-1..base+64
    float* b1s  = xs + 66 * PITCH;          // [64][PITCH]
    float* taps = b1s + TM * PITCH;         // [3][128]

    const int tid  = threadIdx.x;
    const int base = blockIdx.x * TM;

    // Transpose both pointwise weights into smem: Wt[k][o] = w[o][k]
    for (int e = tid; e < CCH * CCH; e += NTHREADS) {
        int o = e >> 7, k = e & 127;
        W1t[k * PITCH + o] = w_pw1[e];
        W2t[k * PITCH + o] = w_pw2[e];
    }
    // Depthwise taps: only kernel column 1 matters (W dim of image is 1)
    for (int e = tid; e < 3 * CCH; e += NTHREADS) {
        int k = e >> 7, c = e & 127;
        taps[e] = w_dw1[c * 9 + k * 3 + 1];
    }
    // x tile with +-1 halo (zero padded at global edges)
    for (int e = tid; e < 66 * 32; e += NTHREADS) {
        int i = e >> 5, q = e & 31;
        long g = (long)base + i - 1;
        float4 v = make_float4(0.f, 0.f, 0.f, 0.f);
        if (g >= 0 && g < NTOK) v = *(const float4*)(x + g * CCH + q * 4);
        *(float4*)(xs + i * PITCH + q * 4) = v;
    }
    __syncthreads();

    // b1 = relu(dw1(x)) on tile rows
    for (int e = tid; e < TM * CCH; e += NTHREADS) {
        int i = e >> 7, c = e & 127;
        float v = taps[c]            * xs[ i      * PITCH + c]
                + taps[CCH + c]      * xs[(i + 1) * PITCH + c]
                + taps[2 * CCH + c]  * xs[(i + 2) * PITCH + c];
        b1s[i * PITCH + c] = fmaxf(v, 0.f);
    }
    __syncthreads();

    const int lane = tid & 31;
    const int r0   = (tid >> 5) * 8;
    const int c0   = lane * 4;

    ull accX[8][2], accB[8][2];
#pragma unroll
    for (int i = 0; i < 8; i++) {
        accX[i][0] = accX[i][1] = 0ull;
        accB[i][0] = accB[i][1] = 0ull;
    }
    gemm_tile(xs + PITCH, W2t, r0, c0, accX);   // t   = x  @ W2^T
    gemm_tile(b1s,        W1t, r0, c0, accB);   // b1p = b1 @ W1^T

#pragma unroll
    for (int i = 0; i < 8; i++) {
        int n = base + r0 + i;
        float2 x0 = unpack2(accX[i][0]), x1 = unpack2(accX[i][1]);
        float2 b0 = unpack2(accB[i][0]), b1 = unpack2(accB[i][1]);
        float v[4];
        v[0] = fmaxf(x0.x, 0.f) + fmaxf(b0.x, 0.f);
        v[1] = fmaxf(x0.y, 0.f) + fmaxf(b0.y, 0.f);
        v[2] = fmaxf(x1.x, 0.f) + fmaxf(b1.x, 0.f);
        v[3] = fmaxf(x1.y, 0.f) + fmaxf(b1.y, 0.f);
#pragma unroll
        for (int j = 0; j < 4; j++) {
            unsigned int fidx = (unsigned)(c0 + j) * (unsigned)NTOK + (unsigned)n;
            if (!keepbit(fidx)) v[j] = 0.f;
        }
        *(float4*)(g_b2 + (size_t)n * CCH + c0) = make_float4(v[0], v[1], v[2], v[3]);
    }
}

// ---------------- Kernel B1: dw2 -> pw3 -> g_b2p ----------------------------
__global__ void __launch_bounds__(NTHREADS)
kB1(const float* __restrict__ w_dw2, const float* __restrict__ w_pw3) {
    extern __shared__ float sm[];
    float* W3t  = sm;                       // [128][PITCH]
    float* b2s  = sm + CCH * PITCH;         // [66][PITCH]
    float* b2ds = b2s + 66 * PITCH;         // [64][PITCH]
    float* taps = b2ds + TM * PITCH;        // [3][128]

    const int tid  = threadIdx.x;
    const int base = blockIdx.x * TM;

    for (int e = tid; e < CCH * CCH; e += NTHREADS) {
        int o = e >> 7, k = e & 127;
        W3t[k * PITCH + o] = w_pw3[e];
    }
    for (int e = tid; e < 3 * CCH; e += NTHREADS) {
        int k = e >> 7, c = e & 127;
        taps[e] = w_dw2[c * 9 + k * 3 + 1];
    }
    for (int e = tid; e < 66 * 32; e += NTHREADS) {
        int i = e >> 5, q = e & 31;
        long g = (long)base + i - 1;
        float4 v = make_float4(0.f, 0.f, 0.f, 0.f);
        if (g >= 0 && g < NTOK) v = *(const float4*)(g_b2 + (size_t)g * CCH + q * 4);
        *(float4*)(b2s + i * PITCH + q * 4) = v;
    }
    __syncthreads();

    for (int e = tid; e < TM * CCH; e += NTHREADS) {
        int i = e >> 7, c = e & 127;
        float v = taps[c]           * b2s[ i      * PITCH + c]
                + taps[CCH + c]     * b2s[(i + 1) * PITCH + c]
                + taps[2 * CCH + c] * b2s[(i + 2) * PITCH + c];
        b2ds[i * PITCH + c] = fmaxf(v, 0.f);
    }
    __syncthreads();

    const int lane = tid & 31;
    const int r0   = (tid >> 5) * 8;
    const int c0   = lane * 4;

    ull acc[8][2];
#pragma unroll
    for (int i = 0; i < 8; i++) acc[i][0] = acc[i][1] = 0ull;
    gemm_tile(b2ds, W3t, r0, c0, acc);

#pragma unroll
    for (int i = 0; i < 8; i++) {
        int n = base + r0 + i;
        float2 p0 = unpack2(acc[i][0]), p1 = unpack2(acc[i][1]);
        *(float4*)(g_b2p + (size_t)n * CCH + c0) =
            make_float4(fmaxf(p0.x, 0.f), fmaxf(p0.y, 0.f),
                        fmaxf(p1.x, 0.f), fmaxf(p1.y, 0.f));
    }
}

// ---------------- Kernel B2: fusion relu(Wf_a x + Wf_b b2p) -> out ----------
__global__ void __launch_bounds__(NTHREADS)
kB2(const float* __restrict__ x, const float* __restrict__ w_f,
    float* __restrict__ out) {
    extern __shared__ float sm[];
    float* Wfat = sm;                       // [128][PITCH]  (wf[:, :128]^T)
    float* Wfbt = sm + CCH * PITCH;         // [128][PITCH]  (wf[:, 128:]^T)
    float* xs   = sm + 2 * CCH * PITCH;     // [64][PITCH]
    float* b2ps = xs + TM * PITCH;          // [64][PITCH]

    const int tid  = threadIdx.x;
    const int base = blockIdx.x * TM;

    for (int e = tid; e < CCH * CCH; e += NTHREADS) {
        int o = e >> 7, k = e & 127;
        Wfat[k * PITCH + o] = w_f[o * 256 + k];
        Wfbt[k * PITCH + o] = w_f[o * 256 + 128 + k];
    }
    for (int e = tid; e < TM * 32; e += NTHREADS) {
        int i = e >> 5, q = e & 31;
        long g = (long)base + i;
        *(float4*)(xs   + i * PITCH + q * 4) = *(const float4*)(x     + g * CCH + q * 4);
        *(float4*)(b2ps + i * PITCH + q * 4) = *(const float4*)(g_b2p + (size_t)g * CCH + q * 4);
    }
    __syncthreads();

    const int lane = tid & 31;
    const int r0   = (tid >> 5) * 8;
    const int c0   = lane * 4;

    ull acc[8][2];
#pragma unroll
    for (int i = 0; i < 8; i++) acc[i][0] = acc[i][1] = 0ull;
    gemm_tile(xs,   Wfat, r0, c0, acc);   // + Wf_a @ x
    gemm_tile(b2ps, Wfbt, r0, c0, acc);   // + Wf_b @ b2p

#pragma unroll
    for (int i = 0; i < 8; i++) {
        int n = base + r0 + i;
        float2 p0 = unpack2(acc[i][0]), p1 = unpack2(acc[i][1]);
        *(float4*)(out + (size_t)n * CCH + c0) =
            make_float4(fmaxf(p0.x, 0.f), fmaxf(p0.y, 0.f),
                        fmaxf(p1.x, 0.f), fmaxf(p1.y, 0.f));
    }
}

// ---------------- launch ----------------------------------------------------
extern "C" void kernel_launch(void* const* d_in, const int* in_sizes, int n_in,
                              void* d_out, int out_size) {
    const float* x        = (const float*)d_in[0];
    const float* w_b1_dw  = (const float*)d_in[1];
    const float* w_b1_pw  = (const float*)d_in[2];
    const float* w_b2_1x1 = (const float*)d_in[3];
    const float* w_b2_dw  = (const float*)d_in[4];
    const float* w_b2_pw  = (const float*)d_in[5];
    const float* w_fusion = (const float*)d_in[6];
    float*       out      = (float*)d_out;

    cudaFuncSetAttribute(kA,  cudaFuncAttributeMaxDynamicSharedMemorySize, SMEM_A);
    cudaFuncSetAttribute(kB1, cudaFuncAttributeMaxDynamicSharedMemorySize, SMEM_B1);
    cudaFuncSetAttribute(kB2, cudaFuncAttributeMaxDynamicSharedMemorySize, SMEM_B2);

    const int grid = NTOK / TM;  // 2048
    kA <<<grid, NTHREADS, SMEM_A >>>(x, w_b1_dw, w_b1_pw, w_b2_1x1);
    kB1<<<grid, NTHREADS, SMEM_B1>>>(w_b2_dw, w_b2_pw);
    kB2<<<grid, NTHREADS, SMEM_B2>>>(x, w_fusion, out);
}

// round 7
// speedup vs baseline: 1.7736x; 1.7736x over previous
#include <cuda_runtime.h>
#include <cuda_bf16.h>

// ----------------------------------------------------------------------------
// KB_Mapping_19361712570541 — mma.sync (HMMA) bf16 hi/lo split implementation.
// (tcgen05 is unavailable: harness PTX target is plain sm_103.)
//   K1: t1 = relu(relu(dw1(x)) @ W1^T)  [smem];  b2 = mask(relu(x@W2^T)+t1)
//   K2: b2p = relu(relu(dw2(b2)) @ W3^T)
//   K3: out = relu(x @ Wfa^T + b2p @ Wfb^T)
// Each GEMM is fp32-accurate via 3-term bf16 split:
//   A@W ~= Ahi@Whi + Ahi@Wlo + Alo@Whi       (~2^-17 rel)
// ----------------------------------------------------------------------------

#define NTOK   131072
#define CCH    128
#define TILE_M 128
#define NTILES (NTOK / TILE_M)   // 1024
#define NT     256
#define PITCHB 136               // bf16 smem pitch (ldmatrix conflict-free)
#define TPITCH 132               // fp32 smem pitch for t1 buffer
#define WBYTES (CCH * PITCHB * 2)   // 34816 per bf16 matrix tile

typedef unsigned int u32;

// ---------------- device scratch ---------------------------------------------
__device__ float g_b2 [(size_t)NTOK * CCH];
__device__ float g_b2p[(size_t)NTOK * CCH];
__device__ __nv_bfloat16 g_whi[5][CCH * CCH];   // row-major [o][k] hi part
__device__ __nv_bfloat16 g_wlo[5][CCH * CCH];   // lo part

// ---------------- PTX helpers -------------------------------------------------
__device__ __forceinline__ u32 smem_u32(const void* p) {
    u32 a;
    asm("{ .reg .u64 t; cvta.to.shared.u64 t, %1; cvt.u32.u64 %0, t; }"
        : "=r"(a) : "l"(p));
    return a;
}
#define LDM4(r, a)                                                          \
    asm volatile("ldmatrix.sync.aligned.m8n8.x4.shared.b16 {%0,%1,%2,%3}, [%4];" \
                 : "=r"((r)[0]), "=r"((r)[1]), "=r"((r)[2]), "=r"((r)[3])   \
                 : "r"(a))
#define MMA(c, a, b0, b1)                                                   \
    asm volatile("mma.sync.aligned.m16n8k16.row.col.f32.bf16.bf16.f32 "     \
                 "{%0,%1,%2,%3}, {%4,%5,%6,%7}, {%8,%9}, {%0,%1,%2,%3};"    \
                 : "+f"((c)[0]), "+f"((c)[1]), "+f"((c)[2]), "+f"((c)[3])   \
                 : "r"((a)[0]), "r"((a)[1]), "r"((a)[2]), "r"((a)[3]),      \
                   "r"(b0), "r"(b1))

// ---------------- threefry-2x32 partitionable keep-bit (validated R5) ---------
__device__ __forceinline__ u32 rotl32(u32 x, int r) { return __funnelshift_l(x, x, r); }
__device__ __forceinline__ u32 keepbit(u32 fidx) {
    const u32 K0 = 0u, K1 = 42u, K2 = 0u ^ 42u ^ 0x1BD11BDAu;
    u32 x0 = 0u + K0;      // counts_hi = 0
    u32 x1 = fidx + K1;    // counts_lo = f
#define TF_R4(a,b,c,d)                               \
    x0 += x1; x1 = rotl32(x1,(a)); x1 ^= x0;         \
    x0 += x1; x1 = rotl32(x1,(b)); x1 ^= x0;         \
    x0 += x1; x1 = rotl32(x1,(c)); x1 ^= x0;         \
    x0 += x1; x1 = rotl32(x1,(d)); x1 ^= x0;
    TF_R4(13,15,26, 6);  x0 += K1; x1 += K2 + 1u;
    TF_R4(17,29,16,24);  x0 += K2; x1 += K0 + 2u;
    TF_R4(13,15,26, 6);  x0 += K0; x1 += K1 + 3u;
    TF_R4(17,29,16,24);  x0 += K1; x1 += K2 + 4u;
    TF_R4(13,15,26, 6);  x0 += K2; x1 += K0 + 5u;
#undef TF_R4
    return (~(x0 ^ x1)) >> 31;   // 1 = keep (MSB of xor-fold == 0)
}

// ---------------- weight prep: bf16 hi/lo split, row-major [o][k] ------------
__global__ void kPrep(const float* __restrict__ w1, const float* __restrict__ w2,
                      const float* __restrict__ w3, const float* __restrict__ wf) {
    int e = blockIdx.x * blockDim.x + threadIdx.x;
    if (e >= 5 * CCH * CCH) return;
    int mat = e >> 14, idx = e & 16383, o = idx >> 7, k = idx & 127;
    float v;
    if      (mat == 0) v = w1[idx];              // w_b1_pw
    else if (mat == 1) v = w2[idx];              // w_b2_1x1
    else if (mat == 2) v = w3[idx];              // w_b2_pw
    else if (mat == 3) v = wf[o * 256 + k];      // w_fusion[:, :128]
    else               v = wf[o * 256 + 128 + k];// w_fusion[:, 128:]
    __nv_bfloat16 h = __float2bfloat16(v);
    __nv_bfloat16 l = __float2bfloat16(v - __bfloat162float(h));
    g_whi[mat][idx] = h;
    g_wlo[mat][idx] = l;
}

// ---------------- tile helpers ------------------------------------------------
__device__ __forceinline__ void load8(float v[8], const float* __restrict__ p,
                                      long row, int k0) {
    if ((unsigned long)row < (unsigned long)NTOK) {
        float4 a = *(const float4*)(p + row * CCH + k0);
        float4 b = *(const float4*)(p + row * CCH + k0 + 4);
        v[0]=a.x; v[1]=a.y; v[2]=a.z; v[3]=a.w;
        v[4]=b.x; v[5]=b.y; v[6]=b.z; v[7]=b.w;
    } else {
#pragma unroll
        for (int j = 0; j < 8; j++) v[j] = 0.f;
    }
}

// Copy one pre-split weight matrix into pitched smem (hi+lo).
__device__ __forceinline__ void loadW(char* hd, char* ld, int mat, int tid) {
    const uint4* sh = (const uint4*)g_whi[mat];
    const uint4* sl = (const uint4*)g_wlo[mat];
#pragma unroll 2
    for (int q = tid; q < 2048; q += NT) {             // 16 uint4 per row
        int n = q >> 4, k0 = (q & 15) << 3;
        u32 doff = (u32)(n * PITCHB + k0) * 2;
        *(uint4*)(hd + doff) = sh[q];
        *(uint4*)(ld + doff) = sl[q];
    }
}

// Fill A tile (optionally fused 3-tap depthwise + relu) as bf16 hi/lo.
__device__ __forceinline__ void fillA(char* Ah, char* Al, const float* __restrict__ src,
                                      int base, const float* taps, int tid) {
#pragma unroll 1
    for (int q = tid; q < 2048; q += NT) {
        int m = q >> 4, k0 = (q & 15) << 3;
        long gr = (long)base + m;
        float v[8];
        if (taps) {
            float a[8], b[8], c[8];
            load8(a, src, gr - 1, k0);
            load8(b, src, gr,     k0);
            load8(c, src, gr + 1, k0);
#pragma unroll
            for (int j = 0; j < 8; j++) {
                int ch = k0 + j;
                v[j] = fmaxf(taps[ch] * a[j] + taps[CCH + ch] * b[j]
                             + taps[2 * CCH + ch] * c[j], 0.f);
            }
        } else {
            load8(v, src, gr, k0);
        }
        uint4 hv, lv;
        unsigned short* hp = (unsigned short*)&hv;
        unsigned short* lp = (unsigned short*)&lv;
#pragma unroll
        for (int j = 0; j < 8; j++) {
            __nv_bfloat16 h = __float2bfloat16(v[j]);
            __nv_bfloat16 l = __float2bfloat16(v[j] - __bfloat162float(h));
            hp[j] = *(unsigned short*)&h;
            lp[j] = *(unsigned short*)&l;
        }
        u32 off = (u32)(m * PITCHB + k0) * 2;
        *(uint4*)(Ah + off) = hv;
        *(uint4*)(Al + off) = lv;
    }
}

// 3-term split GEMM sweep: acc += Ahi@Whi + Ahi@Wlo + Alo@Whi.
// Warp handles rows [m0, m0+16), all 128 cols => acc[16][4].
__device__ __forceinline__ void sweep(u32 ahs, u32 als, u32 whs, u32 wls,
                                      int m0, int lane, float (*acc)[4]) {
    const u32 arow  = (u32)(m0 + (lane & 7) + (lane & 8));
    const u32 acolb = (u32)((lane & 16) >> 1);             // 0 or 8
    const u32 brow0 = (u32)((lane & 7) + ((lane & 16) >> 1));
    const u32 bcolb = (u32)(lane & 8);
#pragma unroll 1
    for (int k = 0; k < 8; k++) {
        u32 aoff = (arow * PITCHB + (u32)k * 16 + acolb) * 2;
        u32 ah[4], al[4];
        LDM4(ah, ahs + aoff);
        LDM4(al, als + aoff);
        u32 bcol = ((u32)k * 16 + bcolb) * 2;
#pragma unroll
        for (int np = 0; np < 8; np++) {
            u32 boff = ((u32)(np * 16) + brow0) * (PITCHB * 2) + bcol;
            u32 bh[4], bl[4];
            LDM4(bh, whs + boff);
            LDM4(bl, wls + boff);
            float* c0 = acc[2 * np];
            float* c1 = acc[2 * np + 1];
            MMA(c0, ah, bh[0], bh[1]);
            MMA(c0, ah, bl[0], bl[1]);
            MMA(c0, al, bh[0], bh[1]);
            MMA(c1, ah, bh[2], bh[3]);
            MMA(c1, ah, bl[2], bl[3]);
            MMA(c1, al, bh[2], bh[3]);
        }
    }
}

// Shared-memory sizes
#define SM1 (6 * WBYTES + 3 * CCH * 4)   // W1 h/l, W2 h/l, A h/l, taps
#define SM2 (4 * WBYTES + 3 * CCH * 4)   // W3 h/l, A h/l, taps
#define SM3 (6 * WBYTES)                 // Wfa h/l, Wfb h/l, A h/l

// ---------------- K1: dw1 -> gemm W1 -> t1(smem); gemm W2; mask -> g_b2 ------
__global__ void __launch_bounds__(NT)
K1(const float* __restrict__ x, const float* __restrict__ wdw) {
    extern __shared__ char sm[];
    char* W1h = sm;                 // later reused as t1 fp32 buffer (67.6KB<=69.6KB)
    char* W1l = sm + WBYTES;
    char* W2h = sm + 2 * WBYTES;
    char* W2l = sm + 3 * WBYTES;
    char* Ah  = sm + 4 * WBYTES;
    char* Al  = sm + 5 * WBYTES;
    float* taps = (float*)(sm + 6 * WBYTES);

    const int tid = threadIdx.x, lane = tid & 31, warp = tid >> 5;
    const int base = blockIdx.x * TILE_M;
    const int m0 = warp * 16, g = lane >> 2, t = lane & 3;

    // phase 1: weights + taps
    loadW(W1h, W1l, 0, tid);
    loadW(W2h, W2l, 1, tid);
    for (int e = tid; e < 3 * CCH; e += NT)
        taps[e] = wdw[(e & 127) * 9 + (e >> 7) * 3 + 1];
    __syncthreads();

    // phase 2: A = relu(dw1(x))
    fillA(Ah, Al, x, base, taps, tid);
    __syncthreads();

    // phase 3: t1 = A @ W1^T
    const u32 ahs = smem_u32(Ah),  als = smem_u32(Al);
    float accT[16][4];
#pragma unroll
    for (int i = 0; i < 16; i++)
#pragma unroll
        for (int j = 0; j < 4; j++) accT[i][j] = 0.f;
    sweep(ahs, als, smem_u32(W1h), smem_u32(W1l), m0, lane, accT);
    __syncthreads();   // everyone done reading W1 / A

    // phase 4: park relu(t1) in smem (over W1); refill A with plain x
    {
        float* T = (float*)sm;
#pragma unroll
        for (int nt = 0; nt < 16; nt++) {
            int c0 = nt * 8 + t * 2;
            *(float2*)(T + (m0 + g) * TPITCH + c0) =
                make_float2(fmaxf(accT[nt][0], 0.f), fmaxf(accT[nt][1], 0.f));
            *(float2*)(T + (m0 + g + 8) * TPITCH + c0) =
                make_float2(fmaxf(accT[nt][2], 0.f), fmaxf(accT[nt][3], 0.f));
        }
    }
    fillA(Ah, Al, x, base, nullptr, tid);
    __syncthreads();

    // phase 5: accX = x @ W2^T
    float accX[16][4];
#pragma unroll
    for (int i = 0; i < 16; i++)
#pragma unroll
        for (int j = 0; j < 4; j++) accX[i][j] = 0.f;
    sweep(ahs, als, smem_u32(W2h), smem_u32(W2l), m0, lane, accX);

    // phase 6: b2 = mask(relu(accX) + t1) -> g_b2
    const float* T = (const float*)sm;
    const int r0 = base + m0 + g;
#pragma unroll 1
    for (int nt = 0; nt < 16; nt++) {
        int c0 = nt * 8 + t * 2;
        float2 t0 = *(const float2*)(T + (m0 + g) * TPITCH + c0);
        float2 t1 = *(const float2*)(T + (m0 + g + 8) * TPITCH + c0);
        float v00 = fmaxf(accX[nt][0], 0.f) + t0.x;
        float v01 = fmaxf(accX[nt][1], 0.f) + t0.y;
        float v10 = fmaxf(accX[nt][2], 0.f) + t1.x;
        float v11 = fmaxf(accX[nt][3], 0.f) + t1.y;
        u32 fc = (u32)c0 << 17;                 // flat = col*131072 + row
        if (!keepbit(fc + (u32)r0))                 v00 = 0.f;
        if (!keepbit(fc + (1u << 17) + (u32)r0))    v01 = 0.f;
        if (!keepbit(fc + (u32)(r0 + 8)))           v10 = 0.f;
        if (!keepbit(fc + (1u << 17) + (u32)(r0 + 8))) v11 = 0.f;
        *(float2*)(g_b2 + (size_t)r0 * CCH + c0)       = make_float2(v00, v01);
        *(float2*)(g_b2 + (size_t)(r0 + 8) * CCH + c0) = make_float2(v10, v11);
    }
}

// ---------------- K2: dw2(b2) -> gemm W3 -> relu -> g_b2p --------------------
__global__ void __launch_bounds__(NT)
K2(const float* __restrict__ wdw) {
    extern __shared__ char sm[];
    char* W3h = sm;
    char* W3l = sm + WBYTES;
    char* Ah  = sm + 2 * WBYTES;
    char* Al  = sm + 3 * WBYTES;
    float* taps = (float*)(sm + 4 * WBYTES);

    const int tid = threadIdx.x, lane = tid & 31, warp = tid >> 5;
    const int base = blockIdx.x * TILE_M;
    const int m0 = warp * 16, g = lane >> 2, t = lane & 3;

    loadW(W3h, W3l, 2, tid);
    for (int e = tid; e < 3 * CCH; e += NT)
        taps[e] = wdw[(e & 127) * 9 + (e >> 7) * 3 + 1];
    __syncthreads();

    fillA(Ah, Al, g_b2, base, taps, tid);
    __syncthreads();

    float acc[16][4];
#pragma unroll
    for (int i = 0; i < 16; i++)
#pragma unroll
        for (int j = 0; j < 4; j++) acc[i][j] = 0.f;
    sweep(smem_u32(Ah), smem_u32(Al), smem_u32(W3h), smem_u32(W3l), m0, lane, acc);

    const int r0 = base + m0 + g;
#pragma unroll
    for (int nt = 0; nt < 16; nt++) {
        int c0 = nt * 8 + t * 2;
        *(float2*)(g_b2p + (size_t)r0 * CCH + c0) =
            make_float2(fmaxf(acc[nt][0], 0.f), fmaxf(acc[nt][1], 0.f));
        *(float2*)(g_b2p + (size_t)(r0 + 8) * CCH + c0) =
            make_float2(fmaxf(acc[nt][2], 0.f), fmaxf(acc[nt][3], 0.f));
    }
}

// ---------------- K3: out = relu(x @ Wfa^T + b2p @ Wfb^T) --------------------
__global__ void __launch_bounds__(NT)
K3(const float* __restrict__ x, float* __restrict__ out) {
    extern __shared__ char sm[];
    char* Wah = sm;
    char* Wal = sm + WBYTES;
    char* Wbh = sm + 2 * WBYTES;
    char* Wbl = sm + 3 * WBYTES;
    char* Ah  = sm + 4 * WBYTES;
    char* Al  = sm + 5 * WBYTES;

    const int tid = threadIdx.x, lane = tid & 31, warp = tid >> 5;
    const int base = blockIdx.x * TILE_M;
    const int m0 = warp * 16, g = lane >> 2, t = lane & 3;

    loadW(Wah, Wal, 3, tid);
    loadW(Wbh, Wbl, 4, tid);
    fillA(Ah, Al, x, base, nullptr, tid);
    __syncthreads();

    const u32 ahs = smem_u32(Ah), als = smem_u32(Al);
    float acc[16][4];
#pragma unroll
    for (int i = 0; i < 16; i++)
#pragma unroll
        for (int j = 0; j < 4; j++) acc[i][j] = 0.f;
    sweep(ahs, als, smem_u32(Wah), smem_u32(Wal), m0, lane, acc);
    __syncthreads();

    fillA(Ah, Al, g_b2p, base, nullptr, tid);
    __syncthreads();
    sweep(ahs, als, smem_u32(Wbh), smem_u32(Wbl), m0, lane, acc);

    const int r0 = base + m0 + g;
#pragma unroll
    for (int nt = 0; nt < 16; nt++) {
        int c0 = nt * 8 + t * 2;
        *(float2*)(out + (size_t)r0 * CCH + c0) =
            make_float2(fmaxf(acc[nt][0], 0.f), fmaxf(acc[nt][1], 0.f));
        *(float2*)(out + (size_t)(r0 + 8) * CCH + c0) =
            make_float2(fmaxf(acc[nt][2], 0.f), fmaxf(acc[nt][3], 0.f));
    }
}

// ---------------- launch ------------------------------------------------------
extern "C" void kernel_launch(void* const* d_in, const int* in_sizes, int n_in,
                              void* d_out, int out_size) {
    const float* x        = (const float*)d_in[0];
    const float* w_b1_dw  = (const float*)d_in[1];
    const float* w_b1_pw  = (const float*)d_in[2];
    const float* w_b2_1x1 = (const float*)d_in[3];
    const float* w_b2_dw  = (const float*)d_in[4];
    const float* w_b2_pw  = (const float*)d_in[5];
    const float* w_fusion = (const float*)d_in[6];
    float*       out      = (float*)d_out;

    cudaFuncSetAttribute(K1, cudaFuncAttributeMaxDynamicSharedMemorySize, SM1);
    cudaFuncSetAttribute(K2, cudaFuncAttributeMaxDynamicSharedMemorySize, SM2);
    cudaFuncSetAttribute(K3, cudaFuncAttributeMaxDynamicSharedMemorySize, SM3);

    kPrep<<<(5 * CCH * CCH + 255) / 256, 256>>>(w_b1_pw, w_b2_1x1, w_b2_pw, w_fusion);
    K1<<<NTILES, NT, SM1>>>(x, w_b1_dw);
    K2<<<NTILES, NT, SM2>>>(w_b2_dw);
    K3<<<NTILES, NT, SM3>>>(x, out);
}

// round 8
// speedup vs baseline: 2.4183x; 1.3635x over previous
#include <cuda_runtime.h>
#include <cuda_bf16.h>

// ----------------------------------------------------------------------------
// KB_Mapping_19361712570541 — mma.sync (HMMA) bf16 hi/lo split, 16-warp CTAs.
//   K1: t1 = relu(relu(dw1(x)) @ W1^T)  [smem];  b2 = mask(relu(x@W2^T)+t1)
//   K2: b2p = relu(relu(dw2(b2)) @ W3^T)
//   K3: out = relu(x @ Wfa^T + b2p @ Wfb^T)
// GEMMs fp32-accurate via 3-term bf16 split: Ahi@Whi + Ahi@Wlo + Alo@Whi.
// Warp map (16 warps): rw=warp&7 -> rows rw*16..+16; cw=warp>>3 -> cols cw*64.
// ----------------------------------------------------------------------------

#define NTOK   131072
#define CCH    128
#define TILE_M 128
#define NTILES (NTOK / TILE_M)   // 1024
#define NT     512
#define PITCHB 136               // bf16 smem pitch (ldmatrix conflict-free)
#define TPITCH 132               // fp32 smem pitch for t1 buffer
#define WBYTES (CCH * PITCHB * 2)   // 34816 per bf16 matrix tile

typedef unsigned int u32;

// ---------------- device scratch ---------------------------------------------
__device__ float g_b2 [(size_t)NTOK * CCH];
__device__ float g_b2p[(size_t)NTOK * CCH];
__device__ __nv_bfloat16 g_whi[5][CCH * CCH];   // row-major [o][k] hi part
__device__ __nv_bfloat16 g_wlo[5][CCH * CCH];   // lo part

// ---------------- PTX helpers -------------------------------------------------
__device__ __forceinline__ u32 smem_u32(const void* p) {
    u32 a;
    asm("{ .reg .u64 t; cvta.to.shared.u64 t, %1; cvt.u32.u64 %0, t; }"
        : "=r"(a) : "l"(p));
    return a;
}
#define LDM4(r, a)                                                          \
    asm volatile("ldmatrix.sync.aligned.m8n8.x4.shared.b16 {%0,%1,%2,%3}, [%4];" \
                 : "=r"((r)[0]), "=r"((r)[1]), "=r"((r)[2]), "=r"((r)[3])   \
                 : "r"(a))
#define MMA(c, a, b0, b1)                                                   \
    asm volatile("mma.sync.aligned.m16n8k16.row.col.f32.bf16.bf16.f32 "     \
                 "{%0,%1,%2,%3}, {%4,%5,%6,%7}, {%8,%9}, {%0,%1,%2,%3};"    \
                 : "+f"((c)[0]), "+f"((c)[1]), "+f"((c)[2]), "+f"((c)[3])   \
                 : "r"((a)[0]), "r"((a)[1]), "r"((a)[2]), "r"((a)[3]),      \
                   "r"(b0), "r"(b1))

// ---------------- threefry-2x32 partitionable keep-bit (validated R5) ---------
__device__ __forceinline__ u32 rotl32(u32 x, int r) { return __funnelshift_l(x, x, r); }
__device__ __forceinline__ u32 keepbit(u32 fidx) {
    const u32 K0 = 0u, K1 = 42u, K2 = 0u ^ 42u ^ 0x1BD11BDAu;
    u32 x0 = 0u + K0;      // counts_hi = 0
    u32 x1 = fidx + K1;    // counts_lo = f
#define TF_R4(a,b,c,d)                               \
    x0 += x1; x1 = rotl32(x1,(a)); x1 ^= x0;         \
    x0 += x1; x1 = rotl32(x1,(b)); x1 ^= x0;         \
    x0 += x1; x1 = rotl32(x1,(c)); x1 ^= x0;         \
    x0 += x1; x1 = rotl32(x1,(d)); x1 ^= x0;
    TF_R4(13,15,26, 6);  x0 += K1; x1 += K2 + 1u;
    TF_R4(17,29,16,24);  x0 += K2; x1 += K0 + 2u;
    TF_R4(13,15,26, 6);  x0 += K0; x1 += K1 + 3u;
    TF_R4(17,29,16,24);  x0 += K1; x1 += K2 + 4u;
    TF_R4(13,15,26, 6);  x0 += K2; x1 += K0 + 5u;
#undef TF_R4
    return (~(x0 ^ x1)) >> 31;   // 1 = keep (MSB of xor-fold == 0)
}

// ---------------- weight prep: bf16 hi/lo split, row-major [o][k] ------------
__global__ void kPrep(const float* __restrict__ w1, const float* __restrict__ w2,
                      const float* __restrict__ w3, const float* __restrict__ wf) {
    int e = blockIdx.x * blockDim.x + threadIdx.x;
    if (e >= 5 * CCH * CCH) return;
    int mat = e >> 14, idx = e & 16383, o = idx >> 7, k = idx & 127;
    float v;
    if      (mat == 0) v = w1[idx];              // w_b1_pw
    else if (mat == 1) v = w2[idx];              // w_b2_1x1
    else if (mat == 2) v = w3[idx];              // w_b2_pw
    else if (mat == 3) v = wf[o * 256 + k];      // w_fusion[:, :128]
    else               v = wf[o * 256 + 128 + k];// w_fusion[:, 128:]
    __nv_bfloat16 h = __float2bfloat16(v);
    __nv_bfloat16 l = __float2bfloat16(v - __bfloat162float(h));
    g_whi[mat][idx] = h;
    g_wlo[mat][idx] = l;
}

// ---------------- tile helpers ------------------------------------------------
__device__ __forceinline__ void load8(float v[8], const float* __restrict__ p,
                                      long row, int k0) {
    if ((unsigned long)row < (unsigned long)NTOK) {
        float4 a = *(const float4*)(p + row * CCH + k0);
        float4 b = *(const float4*)(p + row * CCH + k0 + 4);
        v[0]=a.x; v[1]=a.y; v[2]=a.z; v[3]=a.w;
        v[4]=b.x; v[5]=b.y; v[6]=b.z; v[7]=b.w;
    } else {
#pragma unroll
        for (int j = 0; j < 8; j++) v[j] = 0.f;
    }
}

// Copy one pre-split weight matrix into pitched smem (hi+lo).
__device__ __forceinline__ void loadW(char* hd, char* ld, int mat, int tid) {
    const uint4* sh = (const uint4*)g_whi[mat];
    const uint4* sl = (const uint4*)g_wlo[mat];
#pragma unroll
    for (int q = tid; q < 2048; q += NT) {             // 16 uint4 per row
        int n = q >> 4, k0 = (q & 15) << 3;
        u32 doff = (u32)(n * PITCHB + k0) * 2;
        *(uint4*)(hd + doff) = sh[q];
        *(uint4*)(ld + doff) = sl[q];
    }
}

// Fill A tile (optionally fused 3-tap depthwise + relu) as bf16 hi/lo.
__device__ __forceinline__ void fillA(char* Ah, char* Al, const float* __restrict__ src,
                                      int base, const float* taps, int tid) {
#pragma unroll 1
    for (int q = tid; q < 2048; q += NT) {
        int m = q >> 4, k0 = (q & 15) << 3;
        long gr = (long)base + m;
        float v[8];
        if (taps) {
            float a[8], b[8], c[8];
            load8(a, src, gr - 1, k0);
            load8(b, src, gr,     k0);
            load8(c, src, gr + 1, k0);
#pragma unroll
            for (int j = 0; j < 8; j++) {
                int ch = k0 + j;
                v[j] = fmaxf(taps[ch] * a[j] + taps[CCH + ch] * b[j]
                             + taps[2 * CCH + ch] * c[j], 0.f);
            }
        } else {
            load8(v, src, gr, k0);
        }
        uint4 hv, lv;
        unsigned short* hp = (unsigned short*)&hv;
        unsigned short* lp = (unsigned short*)&lv;
#pragma unroll
        for (int j = 0; j < 8; j++) {
            __nv_bfloat16 h = __float2bfloat16(v[j]);
            __nv_bfloat16 l = __float2bfloat16(v[j] - __bfloat162float(h));
            hp[j] = *(unsigned short*)&h;
            lp[j] = *(unsigned short*)&l;
        }
        u32 off = (u32)(m * PITCHB + k0) * 2;
        *(uint4*)(Ah + off) = hv;
        *(uint4*)(Al + off) = lv;
    }
}

// 3-term split GEMM sweep: acc += Ahi@Whi + Ahi@Wlo + Alo@Whi.
// Warp handles rows [m0, m0+16) x cols [cw*64, cw*64+64) => acc[8][4].
__device__ __forceinline__ void sweep(u32 ahs, u32 als, u32 whs, u32 wls,
                                      int m0, int cw, int lane, float (*acc)[4]) {
    const u32 arow  = (u32)(m0 + (lane & 7) + (lane & 8));
    const u32 acolb = (u32)((lane & 16) >> 1);             // 0 or 8
    const u32 brow0 = (u32)((lane & 7) + ((lane & 16) >> 1));
    const u32 bcolb = (u32)(lane & 8);
#pragma unroll 1
    for (int k = 0; k < 8; k++) {
        u32 aoff = (arow * PITCHB + (u32)k * 16 + acolb) * 2;
        u32 ah[4], al[4];
        LDM4(ah, ahs + aoff);
        LDM4(al, als + aoff);
        u32 bcol = ((u32)k * 16 + bcolb) * 2;
#pragma unroll
        for (int np = 0; np < 4; np++) {
            u32 boff = ((u32)((cw * 4 + np) * 16) + brow0) * (PITCHB * 2) + bcol;
            u32 bh[4], bl[4];
            LDM4(bh, whs + boff);
            LDM4(bl, wls + boff);
            float* c0 = acc[2 * np];
            float* c1 = acc[2 * np + 1];
            MMA(c0, ah, bh[0], bh[1]);
            MMA(c0, ah, bl[0], bl[1]);
            MMA(c0, al, bh[0], bh[1]);
            MMA(c1, ah, bh[2], bh[3]);
            MMA(c1, ah, bl[2], bl[3]);
            MMA(c1, al, bh[2], bh[3]);
        }
    }
}

// Shared-memory sizes
#define SM1 (6 * WBYTES + 3 * CCH * 4)   // W1 h/l, W2 h/l, A h/l, taps
#define SM2 (4 * WBYTES + 3 * CCH * 4)   // W3 h/l, A h/l, taps
#define SM3 (6 * WBYTES)                 // Wfa h/l, Wfb h/l, A h/l

// ---------------- K1: dw1 -> gemm W1 -> t1(smem); gemm W2; mask -> g_b2 ------
__global__ void __launch_bounds__(NT)
K1(const float* __restrict__ x, const float* __restrict__ wdw) {
    extern __shared__ char sm[];
    char* W1h = sm;                 // later reused as t1 fp32 buffer (67.6KB<=69.6KB)
    char* W1l = sm + WBYTES;
    char* W2h = sm + 2 * WBYTES;
    char* W2l = sm + 3 * WBYTES;
    char* Ah  = sm + 4 * WBYTES;
    char* Al  = sm + 5 * WBYTES;
    float* taps = (float*)(sm + 6 * WBYTES);

    const int tid = threadIdx.x, lane = tid & 31, warp = tid >> 5;
    const int base = blockIdx.x * TILE_M;
    const int m0 = (warp & 7) * 16, cw = warp >> 3;
    const int g = lane >> 2, t = lane & 3;

    // phase 1: weights + taps
    loadW(W1h, W1l, 0, tid);
    loadW(W2h, W2l, 1, tid);
    for (int e = tid; e < 3 * CCH; e += NT)
        taps[e] = wdw[(e & 127) * 9 + (e >> 7) * 3 + 1];
    __syncthreads();

    // phase 2: A = relu(dw1(x))
    fillA(Ah, Al, x, base, taps, tid);
    __syncthreads();

    // phase 3: t1 = A @ W1^T
    const u32 ahs = smem_u32(Ah),  als = smem_u32(Al);
    float accT[8][4];
#pragma unroll
    for (int i = 0; i < 8; i++)
#pragma unroll
        for (int j = 0; j < 4; j++) accT[i][j] = 0.f;
    sweep(ahs, als, smem_u32(W1h), smem_u32(W1l), m0, cw, lane, accT);
    __syncthreads();   // everyone done reading W1 / A

    // phase 4: park relu(t1) in smem (over W1); refill A with plain x
    {
        float* T = (float*)sm;
#pragma unroll
        for (int nt = 0; nt < 8; nt++) {
            int c0 = cw * 64 + nt * 8 + t * 2;
            *(float2*)(T + (m0 + g) * TPITCH + c0) =
                make_float2(fmaxf(accT[nt][0], 0.f), fmaxf(accT[nt][1], 0.f));
            *(float2*)(T + (m0 + g + 8) * TPITCH + c0) =
                make_float2(fmaxf(accT[nt][2], 0.f), fmaxf(accT[nt][3], 0.f));
        }
    }
    fillA(Ah, Al, x, base, nullptr, tid);
    __syncthreads();

    // phase 5: accX = x @ W2^T
    float accX[8][4];
#pragma unroll
    for (int i = 0; i < 8; i++)
#pragma unroll
        for (int j = 0; j < 4; j++) accX[i][j] = 0.f;
    sweep(ahs, als, smem_u32(W2h), smem_u32(W2l), m0, cw, lane, accX);

    // phase 6: b2 = mask(relu(accX) + t1) -> g_b2
    const float* T = (const float*)sm;
    const int r0 = base + m0 + g;
#pragma unroll 1
    for (int nt = 0; nt < 8; nt++) {
        int c0 = cw * 64 + nt * 8 + t * 2;
        float2 t0 = *(const float2*)(T + (m0 + g) * TPITCH + c0);
        float2 t1 = *(const float2*)(T + (m0 + g + 8) * TPITCH + c0);
        float v00 = fmaxf(accX[nt][0], 0.f) + t0.x;
        float v01 = fmaxf(accX[nt][1], 0.f) + t0.y;
        float v10 = fmaxf(accX[nt][2], 0.f) + t1.x;
        float v11 = fmaxf(accX[nt][3], 0.f) + t1.y;
        u32 fc = (u32)c0 << 17;                 // flat = col*131072 + row
        if (!keepbit(fc + (u32)r0))                 v00 = 0.f;
        if (!keepbit(fc + (1u << 17) + (u32)r0))    v01 = 0.f;
        if (!keepbit(fc + (u32)(r0 + 8)))           v10 = 0.f;
        if (!keepbit(fc + (1u << 17) + (u32)(r0 + 8))) v11 = 0.f;
        *(float2*)(g_b2 + (size_t)r0 * CCH + c0)       = make_float2(v00, v01);
        *(float2*)(g_b2 + (size_t)(r0 + 8) * CCH + c0) = make_float2(v10, v11);
    }
}

// ---------------- K2: dw2(b2) -> gemm W3 -> relu -> g_b2p --------------------
__global__ void __launch_bounds__(NT)
K2(const float* __restrict__ wdw) {
    extern __shared__ char sm[];
    char* W3h = sm;
    char* W3l = sm + WBYTES;
    char* Ah  = sm + 2 * WBYTES;
    char* Al  = sm + 3 * WBYTES;
    float* taps = (float*)(sm + 4 * WBYTES);

    const int tid = threadIdx.x, lane = tid & 31, warp = tid >> 5;
    const int base = blockIdx.x * TILE_M;
    const int m0 = (warp & 7) * 16, cw = warp >> 3;
    const int g = lane >> 2, t = lane & 3;

    loadW(W3h, W3l, 2, tid);
    for (int e = tid; e < 3 * CCH; e += NT)
        taps[e] = wdw[(e & 127) * 9 + (e >> 7) * 3 + 1];
    __syncthreads();

    fillA(Ah, Al, g_b2, base, taps, tid);
    __syncthreads();

    float acc[8][4];
#pragma unroll
    for (int i = 0; i < 8; i++)
#pragma unroll
        for (int j = 0; j < 4; j++) acc[i][j] = 0.f;
    sweep(smem_u32(Ah), smem_u32(Al), smem_u32(W3h), smem_u32(W3l), m0, cw, lane, acc);

    const int r0 = base + m0 + g;
#pragma unroll
    for (int nt = 0; nt < 8; nt++) {
        int c0 = cw * 64 + nt * 8 + t * 2;
        *(float2*)(g_b2p + (size_t)r0 * CCH + c0) =
            make_float2(fmaxf(acc[nt][0], 0.f), fmaxf(acc[nt][1], 0.f));
        *(float2*)(g_b2p + (size_t)(r0 + 8) * CCH + c0) =
            make_float2(fmaxf(acc[nt][2], 0.f), fmaxf(acc[nt][3], 0.f));
    }
}

// ---------------- K3: out = relu(x @ Wfa^T + b2p @ Wfb^T) --------------------
__global__ void __launch_bounds__(NT)
K3(const float* __restrict__ x, float* __restrict__ out) {
    extern __shared__ char sm[];
    char* Wah = sm;
    char* Wal = sm + WBYTES;
    char* Wbh = sm + 2 * WBYTES;
    char* Wbl = sm + 3 * WBYTES;
    char* Ah  = sm + 4 * WBYTES;
    char* Al  = sm + 5 * WBYTES;

    const int tid = threadIdx.x, lane = tid & 31, warp = tid >> 5;
    const int base = blockIdx.x * TILE_M;
    const int m0 = (warp & 7) * 16, cw = warp >> 3;
    const int g = lane >> 2, t = lane & 3;

    loadW(Wah, Wal, 3, tid);
    loadW(Wbh, Wbl, 4, tid);
    fillA(Ah, Al, x, base, nullptr, tid);
    __syncthreads();

    const u32 ahs = smem_u32(Ah), als = smem_u32(Al);
    float acc[8][4];
#pragma unroll
    for (int i = 0; i < 8; i++)
#pragma unroll
        for (int j = 0; j < 4; j++) acc[i][j] = 0.f;
    sweep(ahs, als, smem_u32(Wah), smem_u32(Wal), m0, cw, lane, acc);
    __syncthreads();

    fillA(Ah, Al, g_b2p, base, nullptr, tid);
    __syncthreads();
    sweep(ahs, als, smem_u32(Wbh), smem_u32(Wbl), m0, cw, lane, acc);

    const int r0 = base + m0 + g;
#pragma unroll
    for (int nt = 0; nt < 8; nt++) {
        int c0 = cw * 64 + nt * 8 + t * 2;
        *(float2*)(out + (size_t)r0 * CCH + c0) =
            make_float2(fmaxf(acc[nt][0], 0.f), fmaxf(acc[nt][1], 0.f));
        *(float2*)(out + (size_t)(r0 + 8) * CCH + c0) =
            make_float2(fmaxf(acc[nt][2], 0.f), fmaxf(acc[nt][3], 0.f));
    }
}

// ---------------- launch ------------------------------------------------------
extern "C" void kernel_launch(void* const* d_in, const int* in_sizes, int n_in,
                              void* d_out, int out_size) {
    const float* x        = (const float*)d_in[0];
    const float* w_b1_dw  = (const float*)d_in[1];
    const float* w_b1_pw  = (const float*)d_in[2];
    const float* w_b2_1x1 = (const float*)d_in[3];
    const float* w_b2_dw  = (const float*)d_in[4];
    const float* w_b2_pw  = (const float*)d_in[5];
    const float* w_fusion = (const float*)d_in[6];
    float*       out      = (float*)d_out;

    cudaFuncSetAttribute(K1, cudaFuncAttributeMaxDynamicSharedMemorySize, SM1);
    cudaFuncSetAttribute(K2, cudaFuncAttributeMaxDynamicSharedMemorySize, SM2);
    cudaFuncSetAttribute(K3, cudaFuncAttributeMaxDynamicSharedMemorySize, SM3);

    kPrep<<<(5 * CCH * CCH + 255) / 256, 256>>>(w_b1_pw, w_b2_1x1, w_b2_pw, w_fusion);
    K1<<<NTILES, NT, SM1>>>(x, w_b1_dw);
    K2<<<NTILES, NT, SM2>>>(w_b2_dw);
    K3<<<NTILES, NT, SM3>>>(x, out);
}